// round 16
// baseline (speedup 1.0000x reference)
#include <cuda_runtime.h>
#include <math.h>
#include <stdint.h>

#define Bk   128
#define Hk   512
#define Tk   1024
#define INk  8
#define OUTk 2

#define JB   8          // j-slice CTAs per batch-group
#define BBL  16         // batch-groups
#define HJ   64         // H / JB
#define BC   8          // batches per CTA
#define NCTA 128
#define NTHR 512        // 16 warps
#define NW   16
#define RPAD 20         // red row stride (floats): 16B-aligned rows for LDS.128
#define STEPS (Tk - 1)

typedef unsigned long long ull;

// ---------------- device globals ----------------
__device__ float g_h[2][BBL][JB][BC * HJ];     // h ping-pong, sliced by producer jb
__device__ int   g_flag[BBL][JB][2][32];       // per-(slice, j-half) flags, 128B lines
__device__ unsigned g_count;
__device__ volatile unsigned g_epoch;

// ---------------- shared memory (~138 KB) ----------------
struct __align__(16) Smem {
    float hbuf[2][BC][Hk];           // staged h, double-buffered           32 KB
    float red[2][BC * HJ][RPAD];     // k-partials, double-buffered         80 KB
    float hist[BC][HJ][8];           // 8-step h history                    16 KB
    float Win[HJ][INk];
    float bias[HJ];
    float Wk[OUTk][Hk];
    float bkey[OUTk];
    float x[2][BC][INk];
};

union F2U { ull u; float2 f; };

__device__ __forceinline__ void fma2(ull& d, ull a, ull b) {
    asm("fma.rn.f32x2 %0, %1, %2, %0;" : "+l"(d) : "l"(a), "l"(b));
}
__device__ __forceinline__ int flag_acquire(const int* fp) {
    int v;
    asm volatile("ld.acquire.gpu.global.s32 %0, [%1];" : "=r"(v) : "l"(fp) : "memory");
    return v;
}
__device__ __forceinline__ void flag_release(int* fp, int v) {
    asm volatile("st.release.gpu.global.s32 [%0], %1;" :: "l"(fp), "r"(v) : "memory");
}
__device__ __forceinline__ void bar_sync_id(int id) {
    asm volatile("bar.sync %0, 256;" :: "r"(id) : "memory");
}
__device__ __forceinline__ void init_grid_barrier() {
    __syncthreads();
    if (threadIdx.x == 0) {
        __threadfence();
        unsigned e = g_epoch;
        if (atomicAdd(&g_count, 1u) == NCTA - 1u) {
            atomicExch(&g_count, 0u);
            __threadfence();
            g_epoch = e + 1u;
        } else {
            while (g_epoch == e) { }
            __threadfence();
        }
    }
    __syncthreads();
}

__global__ void __launch_bounds__(NTHR, 1)
rnn_half_kernel(const float* __restrict__ inputs,   // [B][IN][T]
                const float* __restrict__ W_in,     // [H][IN]
                const float* __restrict__ b_in,
                const float* __restrict__ W_rec,    // [H][H]
                const float* __restrict__ b_rec,
                const float* __restrict__ W_key,    // [OUT][H]
                const float* __restrict__ b_key,
                float* __restrict__ out)
{
    extern __shared__ char smraw[];
    Smem& s = *reinterpret_cast<Smem*>(smraw);

    const int tid = threadIdx.x;
    const int cta = blockIdx.x;
    const int jb  = cta % JB;
    const int bb  = cta / JB;
    const int jg0 = jb * HJ;
    const int bg0 = bb * BC;

    float* keysOut = out;                                             // [B][2][T]
    float* prsOut  = out + (size_t)Bk * 2 * Tk;                       // [B][4][T]
    float* hsOut   = out + (size_t)Bk * 2 * Tk + (size_t)Bk * 4 * Tk; // [B][H][T]

    // ---------------- thread mapping (matvec) ----------------
    const int w    = tid >> 5;           // warp: k-range [32w, 32w+32)
    const int lane = tid & 31;
    const int jq   = lane & 15;          // j-quad: j = jq*4 + jj
    const int ksl  = lane >> 4;          // k sub-half
    const int ks   = 2 * w + ksl;        // thread k2 = ks*8 + i (i<8)
    const int srcSlice = w >> 1;         // producer slice for this warp's k-range
    const int jhalf    = w & 1;          // j-half of that slice this warp consumes

    // finalize mapping: thread -> output o = b*64 + fhalf*32 + jl
    const int fhalf = tid >> 8;          // 0: warps 0-7, 1: warps 8-15
    const int fb    = (tid & 255) >> 5;
    const int fjl   = tid & 31;
    const int fj    = fhalf * 32 + fjl;  // j local to slice
    const int fo    = fb * 64 + fj;      // output index in slice

    // ---------------- register-resident weights ----------------
    ull w2r[8][4];
    {
        #pragma unroll
        for (int jj = 0; jj < 4; ++jj) {
            const float2* row = reinterpret_cast<const float2*>(
                W_rec + (size_t)(jg0 + jq * 4 + jj) * Hk);
            #pragma unroll
            for (int i = 0; i < 8; ++i) {
                F2U u; u.f = row[ks * 8 + i];
                w2r[i][jj] = u.u;
            }
        }
    }

    // ---------------- one-time init ----------------
    for (int idx = tid; idx < HJ * INk; idx += NTHR) {
        int j = idx / INk, i = idx % INk;
        s.Win[j][i] = W_in[(jg0 + j) * INk + i];
    }
    for (int j = tid; j < HJ; j += NTHR)
        s.bias[j] = b_in[jg0 + j] + b_rec[jg0 + j];
    for (int idx = tid; idx < OUTk * Hk; idx += NTHR)
        s.Wk[idx / Hk][idx % Hk] = W_key[idx];
    if (tid < OUTk) s.bkey[tid] = b_key[tid];
    // this CTA owns batch (bg0 + jb) outputs for keys/prs
    if (tid < 2)
        keysOut[(size_t)(bg0 + jb) * 2 * Tk + (size_t)tid * Tk + 0] = 0.f;
    if (tid < 4)
        prsOut[(size_t)(bg0 + jb) * 4 * Tk + (size_t)tid * Tk + 0] = 0.f;
    if (tid < BC * HJ)
        g_h[0][bb][jb][tid] = 0.f;
    s.hist[fb][fj][0] = 0.f;
    // hbuf[0] = h[0] = zeros; stage x column 1
    for (int o = tid; o < BC * Hk; o += NTHR)
        (&s.hbuf[0][0][0])[o] = 0.f;
    if (tid < BC * INk) {
        int b = tid >> 3, i = tid & 7;
        s.x[0][b][i] = inputs[(size_t)(bg0 + b) * INk * Tk + (size_t)i * Tk + 1];
    }
    if (tid < 2) g_flag[bb][jb][tid][0] = 0;
    __syncthreads();
    init_grid_barrier();

    const int* srcFlag = &g_flag[bb][srcSlice][jhalf][0];
    bool staged = false;

    // ================ time loop (hbuf[par] + x[xp] pre-staged) ================
    for (int st = 0; st < STEPS; ++st) {
        const int par = st & 1;
        const int xp  = st & 1;

        // ---- matvec: register weights x broadcast-LDS.128 h[st] ----
        const ulonglong2* hU2 = reinterpret_cast<const ulonglong2*>(&s.hbuf[par][0][0]);
        #pragma unroll
        for (int p = 0; p < 2; ++p) {
            ull acc[4][4];
            #pragma unroll
            for (int bi = 0; bi < 4; ++bi)
                #pragma unroll
                for (int jj = 0; jj < 4; ++jj) acc[bi][jj] = 0ull;

            #pragma unroll
            for (int bi = 0; bi < 4; ++bi) {
                const ulonglong2* hb = &hU2[(p * 4 + bi) * 128 + ks * 4];
                ulonglong2 u0 = hb[0];
                ulonglong2 u1 = hb[1];
                ulonglong2 u2 = hb[2];
                ulonglong2 u3 = hb[3];
                #pragma unroll
                for (int jj = 0; jj < 4; ++jj) {
                    fma2(acc[bi][jj], w2r[0][jj], u0.x);
                    fma2(acc[bi][jj], w2r[1][jj], u0.y);
                    fma2(acc[bi][jj], w2r[2][jj], u1.x);
                    fma2(acc[bi][jj], w2r[3][jj], u1.y);
                    fma2(acc[bi][jj], w2r[4][jj], u2.x);
                    fma2(acc[bi][jj], w2r[5][jj], u2.y);
                    fma2(acc[bi][jj], w2r[6][jj], u3.x);
                    fma2(acc[bi][jj], w2r[7][jj], u3.y);
                }
            }
            #pragma unroll
            for (int bi = 0; bi < 4; ++bi) {
                #pragma unroll
                for (int jj = 0; jj < 4; ++jj) {
                    F2U u; u.u = acc[bi][jj];
                    float f = u.f.x + u.f.y;
                    f += __shfl_xor_sync(0xffffffffu, f, 16);
                    if ((bi >> 1) == ksl) {
                        int b = p * 4 + bi;
                        s.red[par][b * HJ + jq * 4 + jj][w] = f;
                    }
                }
            }
        }
        __syncthreads();   // bar1: red[par] staged (+ all warps' slabs from prev bottom)

        // ---- finalize h[st+1]: per-half, then half-bar + half-release ----
        {
            float v = s.bias[fj];
            const float4* rrow = reinterpret_cast<const float4*>(&s.red[par][fo][0]);
            float4 r0 = rrow[0], r1 = rrow[1], r2 = rrow[2], r3 = rrow[3];
            v += r0.x + r0.y + r0.z + r0.w;
            v += r1.x + r1.y + r1.z + r1.w;
            v += r2.x + r2.y + r2.z + r2.w;
            v += r3.x + r3.y + r3.z + r3.w;
            #pragma unroll
            for (int i = 0; i < INk; ++i) v = fmaf(s.x[xp][fb][i], s.Win[fj][i], v);
            float h = tanhf(v);
            g_h[par ^ 1][bb][jb][fo] = h;
            s.hist[fb][fj][(st + 1) & 7] = h;
        }
        bar_sync_id(3 + fhalf);          // order this half's STGs
        if ((tid & 255) == 0)            // tid 0 -> half0 flag, tid 256 -> half1 flag
            flag_release(&g_flag[bb][jb][fhalf][0], st + 1);

        // ======== slack: key head, x stage, hist flush ========
        if (w < 2) {
            float kv = 1.0f;
            if (st >= 1) {
                const float* hb = &s.hbuf[par][jb][0];
                float acc = 0.f;
                #pragma unroll
                for (int kk = 0; kk < 16; ++kk) {
                    int k = kk * 32 + lane;
                    acc = fmaf(hb[k], s.Wk[w][k], acc);
                }
                acc += __shfl_xor_sync(0xffffffffu, acc, 16);
                acc += __shfl_xor_sync(0xffffffffu, acc, 8);
                acc += __shfl_xor_sync(0xffffffffu, acc, 4);
                acc += __shfl_xor_sync(0xffffffffu, acc, 2);
                acc += __shfl_xor_sync(0xffffffffu, acc, 1);
                float z = acc + s.bkey[w];
                kv = 1.f / (1.f + expf(-z));
                if (lane == 0)
                    keysOut[(size_t)(bg0 + jb) * 2 * Tk + (size_t)w * Tk + st] = kv;
            }
            if (w == 0 && lane < 4) {
                int c = lane;
                float kp = kv;                       // 1.0 at st=0, else key[st-1] (o=0)
                float tm, arm;
                if (c < 2) { tm = s.x[xp][jb][6]; arm = s.x[xp][jb][c]; }
                else       { tm = s.x[xp][jb][7];
                             arm = s.x[xp][jb][c] * kp + s.x[xp][jb][c + 2] * (1.f - kp); }
                float d = (tm - arm) / (0.15f * arm);
                float v = (tm == 0.f) ? 0.f : d * d;
                prsOut[(size_t)(bg0 + jb) * 4 * Tk + (size_t)c * Tk + (st + 1)] = v;
            }
        }

        if (st + 1 < STEPS && tid < BC * INk) {
            int b = tid >> 3, i = tid & 7;
            s.x[xp ^ 1][b][i] =
                inputs[(size_t)(bg0 + b) * INk * Tk + (size_t)i * Tk + (st + 2)];
        }

        if (((st + 1) & 7) == 7) {      // flush own-thread hist slots
            const int base = st - 6;
            float4 lo = *reinterpret_cast<float4*>(&s.hist[fb][fj][0]);
            float4 hi = *reinterpret_cast<float4*>(&s.hist[fb][fj][4]);
            float* dst = &hsOut[(size_t)(bg0 + fb) * Hk * Tk + (size_t)(jg0 + fj) * Tk + base];
            *reinterpret_cast<float4*>(dst)     = lo;
            *reinterpret_cast<float4*>(dst + 4) = hi;
        }

        // ======== wait + stage h[st+1] half-slab into hbuf[par^1] ========
        {
            while (flag_acquire(srcFlag) < st + 1) { }
            const float4* src =
                reinterpret_cast<const float4*>(&g_h[par ^ 1][bb][srcSlice][0]);
            #pragma unroll
            for (int i = 0; i < 2; ++i) {
                int e = lane + 32 * i;       // 0..63 = (b, q)
                int b = e >> 3, q = e & 7;
                float4 v = __ldcg(&src[b * 16 + jhalf * 8 + q]);
                *reinterpret_cast<float4*>(&s.hbuf[par ^ 1][b][w * 32 + q * 4]) = v;
            }
            __syncwarp();
        }
    }

    // ================ epilogue: keys[:,:,1023] for batch (bg0+jb) ================
    {
        const int fpar = STEPS & 1;
        __syncthreads();   // all warps' final slabs visible CTA-wide
        if (w < 2) {
            const float* hb = &s.hbuf[fpar][jb][0];
            float acc = 0.f;
            #pragma unroll
            for (int kk = 0; kk < 16; ++kk) {
                int k = kk * 32 + lane;
                acc = fmaf(hb[k], s.Wk[w][k], acc);
            }
            acc += __shfl_xor_sync(0xffffffffu, acc, 16);
            acc += __shfl_xor_sync(0xffffffffu, acc, 8);
            acc += __shfl_xor_sync(0xffffffffu, acc, 4);
            acc += __shfl_xor_sync(0xffffffffu, acc, 2);
            acc += __shfl_xor_sync(0xffffffffu, acc, 1);
            float z = acc + s.bkey[w];
            float kv = 1.f / (1.f + expf(-z));
            if (lane == 0)
                keysOut[(size_t)(bg0 + jb) * 2 * Tk + (size_t)w * Tk + (Tk - 1)] = kv;
        }
    }
}

extern "C" void kernel_launch(void* const* d_in, const int* in_sizes, int n_in,
                              void* d_out, int out_size) {
    const float* inputs = (const float*)d_in[0];
    const float* W_in   = (const float*)d_in[1];
    const float* b_in   = (const float*)d_in[2];
    const float* W_rec  = (const float*)d_in[3];
    const float* b_rec  = (const float*)d_in[4];
    const float* W_key  = (const float*)d_in[5];
    const float* b_key  = (const float*)d_in[6];
    float* out = (float*)d_out;

    static bool attr_set = false;
    if (!attr_set) {
        cudaFuncSetAttribute(rnn_half_kernel,
                             cudaFuncAttributeMaxDynamicSharedMemorySize,
                             (int)sizeof(Smem));
        attr_set = true;
    }
    rnn_half_kernel<<<NCTA, NTHR, sizeof(Smem)>>>(
        inputs, W_in, b_in, W_rec, b_rec, W_key, b_key, out);
}

// round 17
// speedup vs baseline: 1.4013x; 1.4013x over previous
#include <cuda_runtime.h>
#include <math.h>
#include <stdint.h>

#define Bk   128
#define Hk   512
#define Tk   1024
#define INk  8
#define OUTk 2

#define JB   8          // j-slice CTAs per batch-group
#define BBL  16         // batch-groups
#define HJ   64         // H / JB
#define BC   8          // batches per CTA
#define NCTA 128
#define NTHR 512        // 16 warps
#define NW   16
#define RPAD 17
#define STEPS (Tk - 1)

typedef unsigned long long ull;

// ---------------- device globals ----------------
__device__ float g_h[2][BBL][JB][BC * HJ];     // h ping-pong, sliced by producer jb
__device__ int   g_flag[BBL][JB][32];          // 128B-padded flags
__device__ unsigned g_count;
__device__ volatile unsigned g_epoch;

// ---------------- shared memory (~91 KB) ----------------
struct __align__(16) Smem {
    float hbuf[2][BC][Hk];          // staged h, double-buffered           32 KB
    float red[BC * HJ][RPAD];       // 16 k-partials per output            ~35 KB
    float hist[BC][HJ][8];          // 8-step h history                     16 KB
    float Win[HJ][INk];
    float bias[HJ];
    float Wk[OUTk][Hk];
    float bkey[OUTk];
    float x[2][BC][INk];
};

union F2U { ull u; float2 f; };

__device__ __forceinline__ void fma2(ull& d, ull a, ull b) {
    asm("fma.rn.f32x2 %0, %1, %2, %0;" : "+l"(d) : "l"(a), "l"(b));
}
__device__ __forceinline__ int flag_acquire(const int* fp) {
    int v;
    asm volatile("ld.acquire.gpu.global.s32 %0, [%1];" : "=r"(v) : "l"(fp) : "memory");
    return v;
}
__device__ __forceinline__ void flag_release(int* fp, int v) {
    asm volatile("st.release.gpu.global.s32 [%0], %1;" :: "l"(fp), "r"(v) : "memory");
}
__device__ __forceinline__ void init_grid_barrier() {
    __syncthreads();
    if (threadIdx.x == 0) {
        __threadfence();
        unsigned e = g_epoch;
        if (atomicAdd(&g_count, 1u) == NCTA - 1u) {
            atomicExch(&g_count, 0u);
            __threadfence();
            g_epoch = e + 1u;
        } else {
            while (g_epoch == e) { }
            __threadfence();
        }
    }
    __syncthreads();
}

__global__ void __launch_bounds__(NTHR, 1)
rnn_local_kernel(const float* __restrict__ inputs,   // [B][IN][T]
                 const float* __restrict__ W_in,     // [H][IN]
                 const float* __restrict__ b_in,
                 const float* __restrict__ W_rec,    // [H][H]
                 const float* __restrict__ b_rec,
                 const float* __restrict__ W_key,    // [OUT][H]
                 const float* __restrict__ b_key,
                 float* __restrict__ out)
{
    extern __shared__ char smraw[];
    Smem& s = *reinterpret_cast<Smem*>(smraw);

    const int tid = threadIdx.x;
    const int cta = blockIdx.x;
    const int jb  = cta % JB;
    const int bb  = cta / JB;
    const int jg0 = jb * HJ;
    const int bg0 = bb * BC;

    float* keysOut = out;                                             // [B][2][T]
    float* prsOut  = out + (size_t)Bk * 2 * Tk;                       // [B][4][T]
    float* hsOut   = out + (size_t)Bk * 2 * Tk + (size_t)Bk * 4 * Tk; // [B][H][T]

    // ---------------- thread mapping ----------------
    const int w    = tid >> 5;           // warp: k-range [32w, 32w+32)
    const int lane = tid & 31;
    const int jq   = lane & 15;          // j-quad: j = jq*4 + jj
    const int ksl  = lane >> 4;          // k sub-half
    const int ks   = 2 * w + ksl;        // thread k2 = ks*8 + i (i<8)
    const int srcSlice = w >> 1;         // producer slice for this warp's k-range
    const int jhalf    = w & 1;
    const bool ownSlice = (srcSlice == jb);   // own CTA produces this warp's slab

    // ---------------- register-resident weights ----------------
    ull w2r[8][4];
    {
        #pragma unroll
        for (int jj = 0; jj < 4; ++jj) {
            const float2* row = reinterpret_cast<const float2*>(
                W_rec + (size_t)(jg0 + jq * 4 + jj) * Hk);
            #pragma unroll
            for (int i = 0; i < 8; ++i) {
                F2U u; u.f = row[ks * 8 + i];
                w2r[i][jj] = u.u;
            }
        }
    }

    // ---------------- one-time init ----------------
    for (int idx = tid; idx < HJ * INk; idx += NTHR) {
        int j = idx / INk, i = idx % INk;
        s.Win[j][i] = W_in[(jg0 + j) * INk + i];
    }
    for (int j = tid; j < HJ; j += NTHR)
        s.bias[j] = b_in[jg0 + j] + b_rec[jg0 + j];
    for (int idx = tid; idx < OUTk * Hk; idx += NTHR)
        s.Wk[idx / Hk][idx % Hk] = W_key[idx];
    if (tid < OUTk) s.bkey[tid] = b_key[tid];
    // this CTA owns batch (bg0 + jb) outputs for keys/prs
    if (tid < 2)
        keysOut[(size_t)(bg0 + jb) * 2 * Tk + (size_t)tid * Tk + 0] = 0.f;
    if (tid < 4)
        prsOut[(size_t)(bg0 + jb) * 4 * Tk + (size_t)tid * Tk + 0] = 0.f;
    if (tid < BC * HJ) {
        g_h[0][bb][jb][tid] = 0.f;
        int b = tid >> 6, j = tid & 63;
        s.hist[b][j][0] = 0.f;
    }
    if (tid == 0) g_flag[bb][jb][0] = 0;
    __syncthreads();
    init_grid_barrier();

    const int* srcFlag = &g_flag[bb][srcSlice][0];
    bool staged = false;

    // ================ time loop ================
    for (int st = 0; st < STEPS; ++st) {
        const int par = st & 1;
        const int xp  = st & 1;

        // stage input column st+1
        if (tid < BC * INk) {
            int b = tid >> 3, i = tid & 7;
            s.x[xp][b][i] = inputs[(size_t)(bg0 + b) * INk * Tk + (size_t)i * Tk + (st + 1)];
        }

        // ---- stage h[st] slab unless already early-staged last step ----
        if (!staged) {
            while (flag_acquire(srcFlag) < st) { }
            const float4* src = reinterpret_cast<const float4*>(&g_h[par][bb][srcSlice][0]);
            #pragma unroll
            for (int i = 0; i < 2; ++i) {
                int e = lane + 32 * i;       // 0..63 = (b, q)
                int b = e >> 3, q = e & 7;
                float4 v = __ldcg(&src[b * 16 + jhalf * 8 + q]);
                *reinterpret_cast<float4*>(&s.hbuf[par][b][w * 32 + q * 4]) = v;
            }
        }
        staged = false;
        __syncwarp();

        // ---- matvec: register weights x broadcast-LDS.128 h ----
        const ulonglong2* hU2 = reinterpret_cast<const ulonglong2*>(&s.hbuf[par][0][0]);
        #pragma unroll
        for (int p = 0; p < 2; ++p) {
            ull acc[4][4];
            #pragma unroll
            for (int bi = 0; bi < 4; ++bi)
                #pragma unroll
                for (int jj = 0; jj < 4; ++jj) acc[bi][jj] = 0ull;

            #pragma unroll
            for (int bi = 0; bi < 4; ++bi) {
                const ulonglong2* hb = &hU2[(p * 4 + bi) * 128 + ks * 4];
                ulonglong2 u0 = hb[0];
                ulonglong2 u1 = hb[1];
                ulonglong2 u2 = hb[2];
                ulonglong2 u3 = hb[3];
                #pragma unroll
                for (int jj = 0; jj < 4; ++jj) {
                    fma2(acc[bi][jj], w2r[0][jj], u0.x);
                    fma2(acc[bi][jj], w2r[1][jj], u0.y);
                    fma2(acc[bi][jj], w2r[2][jj], u1.x);
                    fma2(acc[bi][jj], w2r[3][jj], u1.y);
                    fma2(acc[bi][jj], w2r[4][jj], u2.x);
                    fma2(acc[bi][jj], w2r[5][jj], u2.y);
                    fma2(acc[bi][jj], w2r[6][jj], u3.x);
                    fma2(acc[bi][jj], w2r[7][jj], u3.y);
                }
            }
            #pragma unroll
            for (int bi = 0; bi < 4; ++bi) {
                #pragma unroll
                for (int jj = 0; jj < 4; ++jj) {
                    F2U u; u.u = acc[bi][jj];
                    float f = u.f.x + u.f.y;
                    f += __shfl_xor_sync(0xffffffffu, f, 16);
                    if ((bi >> 1) == ksl) {
                        int b = p * 4 + bi;
                        s.red[b * HJ + jq * 4 + jj][w] = f;
                    }
                }
            }
        }
        __syncthreads();   // bar1: red + x staged

        // ---- finalize h[st+1]: one output per thread ----
        {
            int b = tid >> 6, j = tid & 63;
            float v = s.bias[j];
            #pragma unroll
            for (int kw = 0; kw < NW; ++kw) v += s.red[tid][kw];
            #pragma unroll
            for (int i = 0; i < INk; ++i) v = fmaf(s.x[xp][b][i], s.Win[j][i], v);
            float h = tanhf(v);
            g_h[par ^ 1][bb][jb][tid] = h;
            s.hist[b][j][(st + 1) & 7] = h;
        }
        __syncthreads();   // bar2: h STGs + hist done

        // publish (padded flag line)
        if (tid == 0) flag_release(&g_flag[bb][jb][0], st + 1);

        // ---- own-slice warps: stage h[st+1] slab from local hist (no flag, no LDG) ----
        if (ownSlice) {
            const int slot = (st + 1) & 7;
            #pragma unroll
            for (int i = 0; i < 2; ++i) {
                int e = lane + 32 * i;       // 0..63 = (b, jl)
                int b = e >> 3, jl = (e & 7) * 4 + 0;
                int j0 = jhalf * 32 + (e & 7) * 4;
                float4 v = make_float4(s.hist[b][j0 + 0][slot], s.hist[b][j0 + 1][slot],
                                       s.hist[b][j0 + 2][slot], s.hist[b][j0 + 3][slot]);
                (void)jl;
                *reinterpret_cast<float4*>(&s.hbuf[par ^ 1][b][w * 32 + (e & 7) * 4]) = v;
            }
            staged = true;
        }

        // ---- distributed key head: this CTA handles batch jb (warps 0,1) ----
        if (w < 2) {
            float kv = 1.0f;
            if (st >= 1) {
                const float* hb = &s.hbuf[par][jb][0];
                float acc = 0.f;
                #pragma unroll
                for (int kk = 0; kk < 16; ++kk) {
                    int k = kk * 32 + lane;
                    acc = fmaf(hb[k], s.Wk[w][k], acc);
                }
                acc += __shfl_xor_sync(0xffffffffu, acc, 16);
                acc += __shfl_xor_sync(0xffffffffu, acc, 8);
                acc += __shfl_xor_sync(0xffffffffu, acc, 4);
                acc += __shfl_xor_sync(0xffffffffu, acc, 2);
                acc += __shfl_xor_sync(0xffffffffu, acc, 1);
                float z = acc + s.bkey[w];
                kv = 1.f / (1.f + expf(-z));
                if (lane == 0)
                    keysOut[(size_t)(bg0 + jb) * 2 * Tk + (size_t)w * Tk + st] = kv;
            }
            if (w == 0 && lane < 4) {
                int c = lane;
                float kp = kv;                       // 1.0 at st=0, else key[st-1] (o=0)
                float tm, arm;
                if (c < 2) { tm = s.x[xp][jb][6]; arm = s.x[xp][jb][c]; }
                else       { tm = s.x[xp][jb][7];
                             arm = s.x[xp][jb][c] * kp + s.x[xp][jb][c + 2] * (1.f - kp); }
                float d = (tm - arm) / (0.15f * arm);
                float v = (tm == 0.f) ? 0.f : d * d;
                prsOut[(size_t)(bg0 + jb) * 4 * Tk + (size_t)c * Tk + (st + 1)] = v;
            }
        }

        // ---- flush 8-step history (same-thread slots) ----
        if (((st + 1) & 7) == 7) {
            const int base = st - 6;
            int b = tid >> 6, j = tid & 63;
            float4 lo = *reinterpret_cast<float4*>(&s.hist[b][j][0]);
            float4 hi = *reinterpret_cast<float4*>(&s.hist[b][j][4]);
            float* dst = &hsOut[(size_t)(bg0 + b) * Hk * Tk + (size_t)(jg0 + j) * Tk + base];
            *reinterpret_cast<float4*>(dst)     = lo;
            *reinterpret_cast<float4*>(dst + 4) = hi;
        }

        // ---- speculative early-stage of h[st+1] (remote slices; latest point) ----
        if (!ownSlice) {
            int v = flag_acquire(srcFlag);
            if (__all_sync(0xffffffffu, v >= st + 1)) {
                const float4* src =
                    reinterpret_cast<const float4*>(&g_h[par ^ 1][bb][srcSlice][0]);
                #pragma unroll
                for (int i = 0; i < 2; ++i) {
                    int e = lane + 32 * i;
                    int b = e >> 3, q = e & 7;
                    float4 vv = __ldcg(&src[b * 16 + jhalf * 8 + q]);
                    *reinterpret_cast<float4*>(&s.hbuf[par ^ 1][b][w * 32 + q * 4]) = vv;
                }
                staged = true;
            }
        }
    }

    // ================ epilogue: keys[:,:,1023] for batch (bg0+jb) ================
    {
        const int fpar = STEPS & 1;
        if (!staged) {
            while (flag_acquire(srcFlag) < STEPS) { }
            const float4* src = reinterpret_cast<const float4*>(&g_h[fpar][bb][srcSlice][0]);
            #pragma unroll
            for (int i = 0; i < 2; ++i) {
                int e = lane + 32 * i;
                int b = e >> 3, q = e & 7;
                float4 v = __ldcg(&src[b * 16 + jhalf * 8 + q]);
                *reinterpret_cast<float4*>(&s.hbuf[fpar][b][w * 32 + q * 4]) = v;
            }
        }
        __syncthreads();
        if (w < 2) {
            const float* hb = &s.hbuf[fpar][jb][0];
            float acc = 0.f;
            #pragma unroll
            for (int kk = 0; kk < 16; ++kk) {
                int k = kk * 32 + lane;
                acc = fmaf(hb[k], s.Wk[w][k], acc);
            }
            acc += __shfl_xor_sync(0xffffffffu, acc, 16);
            acc += __shfl_xor_sync(0xffffffffu, acc, 8);
            acc += __shfl_xor_sync(0xffffffffu, acc, 4);
            acc += __shfl_xor_sync(0xffffffffu, acc, 2);
            acc += __shfl_xor_sync(0xffffffffu, acc, 1);
            float z = acc + s.bkey[w];
            float kv = 1.f / (1.f + expf(-z));
            if (lane == 0)
                keysOut[(size_t)(bg0 + jb) * 2 * Tk + (size_t)w * Tk + (Tk - 1)] = kv;
        }
    }
}

extern "C" void kernel_launch(void* const* d_in, const int* in_sizes, int n_in,
                              void* d_out, int out_size) {
    const float* inputs = (const float*)d_in[0];
    const float* W_in   = (const float*)d_in[1];
    const float* b_in   = (const float*)d_in[2];
    const float* W_rec  = (const float*)d_in[3];
    const float* b_rec  = (const float*)d_in[4];
    const float* W_key  = (const float*)d_in[5];
    const float* b_key  = (const float*)d_in[6];
    float* out = (float*)d_out;

    static bool attr_set = false;
    if (!attr_set) {
        cudaFuncSetAttribute(rnn_local_kernel,
                             cudaFuncAttributeMaxDynamicSharedMemorySize,
                             (int)sizeof(Smem));
        attr_set = true;
    }
    rnn_local_kernel<<<NCTA, NTHR, sizeof(Smem)>>>(
        inputs, W_in, b_in, W_rec, b_rec, W_key, b_key, out);
}